// round 8
// baseline (speedup 1.0000x reference)
#include <cuda_runtime.h>
#include <stdint.h>

#define NROWS 500000
#define TPB   256
#define ROWS_PER_BLOCK 32     // 8 warps * 4 rows

template<class T> __device__ __forceinline__ T vmax(T a, T b) { return a > b ? a : b; }
template<class T> __device__ __forceinline__ T vmin(T a, T b) { return a < b ? a : b; }

// fixed-direction CE: first slot keeps max (descending)
template<class T> __device__ __forceinline__ void ceF(T& a, T& b) {
    T h = vmax(a, b), l = vmin(a, b); a = h; b = l;
}

// in-lane Batcher odd-even mergesort-8, descending (19 CEs, all fixed)
template<class T> __device__ __forceinline__ void sort8(T K[8]) {
    ceF(K[0],K[1]); ceF(K[2],K[3]); ceF(K[4],K[5]); ceF(K[6],K[7]);
    ceF(K[0],K[2]); ceF(K[1],K[3]); ceF(K[4],K[6]); ceF(K[5],K[7]);
    ceF(K[1],K[2]); ceF(K[5],K[6]);
    ceF(K[0],K[4]); ceF(K[1],K[5]); ceF(K[2],K[6]); ceF(K[3],K[7]);
    ceF(K[2],K[4]); ceF(K[3],K[5]);
    ceF(K[1],K[2]); ceF(K[3],K[4]); ceF(K[5],K[6]);
}

// in-lane bitonic merge-8 (bitonic input -> sorted desc), 12 CEs fixed
template<class T> __device__ __forceinline__ void bmerge8(T K[8]) {
    ceF(K[0],K[4]); ceF(K[1],K[5]); ceF(K[2],K[6]); ceF(K[3],K[7]);
    ceF(K[0],K[2]); ceF(K[1],K[3]); ceF(K[4],K[6]); ceF(K[5],K[7]);
    ceF(K[0],K[1]); ceF(K[2],K[3]); ceF(K[4],K[5]); ceF(K[6],K[7]);
}

// cross-lane reversed CE at distance d, predicated (keepMax per lane)
// reads ALL partner values before writing (no RAW hazard)
template<class T> __device__ __forceinline__ void crossRevPred(T K[8], int d, bool km, unsigned m) {
    T q[8];
    #pragma unroll
    for (int r = 0; r < 8; r++) q[r] = __shfl_xor_sync(m, K[7 - r], d);
    #pragma unroll
    for (int r = 0; r < 8; r++) K[r] = km ? vmax(K[r], q[r]) : vmin(K[r], q[r]);
}

// cross-lane reversed prune: keep max BOTH sides; optionally capture max of the
// discarded mins. All partner values are read BEFORE any write — the previous
// in-loop version fed already-maxed values into the min capture, corrupting key16.
template<class T, bool CAP>
__device__ __forceinline__ void crossRevMax(T K[8], int d, unsigned m, T* mMin) {
    T q[8];
    #pragma unroll
    for (int r = 0; r < 8; r++) q[r] = __shfl_xor_sync(m, K[7 - r], d);
    T run;
    #pragma unroll
    for (int r = 0; r < 8; r++) {
        if (CAP) { T l = vmin(K[r], q[r]); run = (r == 0) ? l : vmax(run, l); }
        K[r] = vmax(K[r], q[r]);
    }
    if (CAP) *mMin = run;
}

// cross-lane straight CE at distance d, predicated (no hazard: reads/writes same reg)
template<class T> __device__ __forceinline__ void crossPred(T K[8], int d, bool km, unsigned m) {
    #pragma unroll
    for (int r = 0; r < 8; r++) {
        T q = __shfl_xor_sync(m, K[r], d);
        K[r] = km ? vmax(K[r], q) : vmin(K[r], q);
    }
}

// Top-16-of-64. Input: lane s (within 8-lane group) holds elements 8s..8s+7 in K.
// Output: every lane-pair holds sorted top-16; lane b=s&1 holds positions 8b..8b+7.
template<class T, bool CAP>
__device__ __forceinline__ void top16net(T K[8], bool P1, unsigned m, T* mMin) {
    sort8(K);
    crossRevPred(K, 1, P1, m);  bmerge8(K);                    // sorted-16 per pair
    crossRevMax<T,false>(K, 3, m, (T*)nullptr);                // prune 32->16
    crossPred(K, 1, P1, m);     bmerge8(K);                    // resorted-16
    crossRevMax<T,CAP>(K, 5, m, mMin);                         // prune 32->16 (capture 17th)
    crossPred(K, 1, P1, m);     bmerge8(K);                    // final sorted top-16
}

__global__ __launch_bounds__(TPB, 6)
void vns_kernel(const float* __restrict__ x, float* __restrict__ out) {
    const int lane = threadIdx.x & 31;
    const int s    = lane & 7;                         // sublane within row group
    const int row  = blockIdx.x * ROWS_PER_BLOCK + (threadIdx.x >> 5) * 4 + (lane >> 3);
    const bool P1  = (s & 1) == 0;
    const int  b   = s & 1;
    const int  q   = s >> 1;                           // 0..3

    // ---- load: lane holds elements 8s..8s+7 = floats [24s, 24s+24) : 6 x float4 ----
    const float* __restrict__ xrow = x + (size_t)row * 192;
    const float4* p4 = (const float4*)xrow + 6 * s;
    float F[24];
    #pragma unroll
    for (int i = 0; i < 6; i++) *(float4*)(&F[4 * i]) = p4[i];

    // ---- squared norms, bit-matching ((x*x + y*y) + z*z); 32-bit keys ----
    const unsigned b63 = 63 - 8 * s;
    unsigned K[8];
    #pragma unroll
    for (int j = 0; j < 8; j++) {
        float a = F[3 * j], bb = F[3 * j + 1], c = F[3 * j + 2];
        float n = __fadd_rn(__fadd_rn(__fmul_rn(a, a), __fmul_rn(bb, bb)), __fmul_rn(c, c));
        K[j] = (__float_as_uint(n) & 0xFFFFFFC0u) | (b63 - j);
    }

    unsigned mMin;
    top16net<unsigned, true>(K, P1, 0xffffffffu, &mMin);
    // 17th-largest trunc-key across the pair:
    unsigned key16 = vmax(mMin, __shfl_xor_sync(0xffffffffu, mMin, 1));

    // ---- exactness checks: adjacent trunc-equal over sorted positions 0..16 ----
    bool bad = false;
    #pragma unroll
    for (int r = 0; r < 7; r++) bad |= (((K[r] ^ K[r + 1]) >> 6) == 0);
    unsigned nb = __shfl_xor_sync(0xffffffffu, K[0], 1);   // partner's first position
    unsigned bcmp = b ? key16 : nb;                        // b=0: pos7 vs pos8; b=1: pos15 vs key16
    bad |= (((K[7] ^ bcmp) >> 6) == 0);
    unsigned bal = __ballot_sync(0xffffffffu, bad);
    bool groupBad = ((bal >> (lane & 24)) & 0xFFu) != 0;

    float* __restrict__ orow = out + (size_t)row * 48;
    const int p0 = 8 * b + 2 * q;

    if (!groupBad) {
        // ---- fast path: emit positions p0, p0+1 from own registers ----
        unsigned t0 = (q & 1) ? K[2] : K[0];
        unsigned t1 = (q & 1) ? K[6] : K[4];
        unsigned Kp0 = (q & 2) ? t1 : t0;
        unsigned u0 = (q & 1) ? K[3] : K[1];
        unsigned u1 = (q & 1) ? K[7] : K[5];
        unsigned Kp1 = (q & 2) ? u1 : u0;
        int idx0 = 63 - (int)(Kp0 & 63u);
        int idx1 = 63 - (int)(Kp1 & 63u);
        const float* v0 = xrow + 3 * idx0;               // L1-resident re-read
        const float* v1 = xrow + 3 * idx1;
        orow[3 * p0 + 0] = v0[0];
        orow[3 * p0 + 1] = v0[1];
        orow[3 * p0 + 2] = v0[2];
        orow[3 * p0 + 3] = v1[0];
        orow[3 * p0 + 4] = v1[1];
        orow[3 * p0 + 5] = v1[2];
    } else {
        // ---- exact fallback (rare, per 8-lane group): 64-bit (norm, idx) keys ----
        const unsigned gm = 0xFFu << (lane & 24);
        unsigned long long A[8];
        #pragma unroll
        for (int j = 0; j < 8; j++) {
            float a = F[3 * j], bb = F[3 * j + 1], c = F[3 * j + 2];
            float n = __fadd_rn(__fadd_rn(__fmul_rn(a, a), __fmul_rn(bb, bb)), __fmul_rn(c, c));
            A[j] = ((unsigned long long)__float_as_uint(n) << 32) | (unsigned long long)(b63 - j);
        }
        top16net<unsigned long long, false>(A, P1, gm, (unsigned long long*)nullptr);
        unsigned long long t0 = (q & 1) ? A[2] : A[0];
        unsigned long long t1 = (q & 1) ? A[6] : A[4];
        unsigned long long Kp0 = (q & 2) ? t1 : t0;
        unsigned long long u0 = (q & 1) ? A[3] : A[1];
        unsigned long long u1 = (q & 1) ? A[7] : A[5];
        unsigned long long Kp1 = (q & 2) ? u1 : u0;
        int idx0 = 63 - (int)(Kp0 & 63ull);
        int idx1 = 63 - (int)(Kp1 & 63ull);
        const float* v0 = xrow + 3 * idx0;
        const float* v1 = xrow + 3 * idx1;
        orow[3 * p0 + 0] = v0[0];
        orow[3 * p0 + 1] = v0[1];
        orow[3 * p0 + 2] = v0[2];
        orow[3 * p0 + 3] = v1[0];
        orow[3 * p0 + 4] = v1[1];
        orow[3 * p0 + 5] = v1[2];
    }
}

extern "C" void kernel_launch(void* const* d_in, const int* in_sizes, int n_in,
                              void* d_out, int out_size) {
    const float* x = (const float*)d_in[0];
    float* out = (float*)d_out;
    vns_kernel<<<NROWS / ROWS_PER_BLOCK, TPB>>>(x, out);
}